// round 7
// baseline (speedup 1.0000x reference)
#include <cuda_runtime.h>
#include <cuda_fp16.h>
#include <cstdint>

// ---------------------------------------------------------------------------
// ModalityRouter via mma.sync m16n8k16.f16 with 2-limb fp32 split (3 products)
// Warp tile M=32 x N=64 (all experts): A rows loaded & split ONCE per CTA.
// B stored fragment-major: one coalesced LDG.128 yields both limb fragments.
//   logits = x @ gate_w^T ; top-2 ; softmax ; expert load
//   x: [32768, 2048] fp32   gate_w: [64, 2048] fp32
// Output fp32: gates[65536] | idx[65536] | load[64] | top_logits[65536]
// ---------------------------------------------------------------------------

#define DK        2048
#define NE        64
#define NTOK      32768
#define BM        128
#define NTHREADS  128
#define NGROUPS   (DK / 16)      // 128 groups of 16 k-columns

// fragment-major fp16 limb split of gate_w:
//   g_Bfrag[(g*8 + nt)*32 + lane] = {hi.x, hi.y, lo.x, lo.y}
//   lane=(gid*4+tig) holds halves k = g*16 + perm(tig*4..+3) of expert
//   e = nt*8 + gid   (same k-permutation as the A fragments)
__device__ uint4 g_Bfrag[NGROUPS * 8 * 32];     // 512 KB

__device__ __forceinline__ uint32_t pack_h2(float a, float b) {
    __half2 h = __halves2half2(__float2half_rn(a), __float2half_rn(b));
    return *reinterpret_cast<uint32_t*>(&h);
}

__global__ void prep_kernel(const float* __restrict__ w, float* __restrict__ out_load) {
    const int t = blockIdx.x * 256 + threadIdx.x;    // 32768 threads total
    if (blockIdx.x == 0 && threadIdx.x < NE) out_load[threadIdx.x] = 0.0f;

    const int lane = t & 31;
    const int nt   = (t >> 5) & 7;                   // n-tile 0..7
    const int g    = t >> 8;                         // k-group 0..127
    const int gid  = lane >> 2;
    const int tig  = lane & 3;
    const int e    = nt * 8 + gid;
    const int kb   = g * 16 + tig * 4;

    float4 v = *reinterpret_cast<const float4*>(w + (size_t)e * DK + kb);
    float hx = __half2float(__float2half_rn(v.x));
    float hy = __half2float(__float2half_rn(v.y));
    float hz = __half2float(__float2half_rn(v.z));
    float hw = __half2float(__float2half_rn(v.w));

    uint4 frag;
    frag.x = pack_h2(v.x, v.y);                 // hi limb, k {4t, 4t+1}
    frag.y = pack_h2(v.z, v.w);                 // hi limb, k {4t+2, 4t+3}
    frag.z = pack_h2(v.x - hx, v.y - hy);       // lo limb
    frag.w = pack_h2(v.z - hz, v.w - hw);
    g_Bfrag[t] = frag;
}

// warp-level tensor op: D += A(f16) * B(f16), f32 accumulate
__device__ __forceinline__ void mma16(float* d, const uint32_t* a,
                                      uint32_t b0, uint32_t b1) {
    asm volatile(
        "mma.sync.aligned.m16n8k16.row.col.f32.f16.f16.f32 "
        "{%0,%1,%2,%3}, {%4,%5,%6,%7}, {%8,%9}, {%0,%1,%2,%3};"
        : "+f"(d[0]), "+f"(d[1]), "+f"(d[2]), "+f"(d[3])
        : "r"(a[0]), "r"(a[1]), "r"(a[2]), "r"(a[3]), "r"(b0), "r"(b1));
}

// split a float2 into (hi half2, lo half2)
__device__ __forceinline__ void split2(float2 f, uint32_t& hi, uint32_t& lo) {
    __half2 h = __float22half2_rn(f);
    float2 hf = __half22float2(h);
    __half2 l = __float22half2_rn(make_float2(f.x - hf.x, f.y - hf.y));
    hi = *reinterpret_cast<uint32_t*>(&h);
    lo = *reinterpret_cast<uint32_t*>(&l);
}

// ---------------------------------------------------------------------------
__global__ void __launch_bounds__(NTHREADS, 2)
router_kernel(const float* __restrict__ x, float* __restrict__ out)
{
    __shared__ float lg[BM][NE + 1];
    __shared__ float sg[2 * BM];
    __shared__ int   si[2 * BM];

    const int tid    = threadIdx.x;
    const int wid    = tid >> 5;        // token slice (0..3): 32 tokens each
    const int lane   = tid & 31;
    const int gid    = lane >> 2;       // fragment row/col group (0..7)
    const int tig    = lane & 3;        // thread-in-group (0..3)
    const int tok0   = blockIdx.x * BM;

    // A pointer (k-permutation {2t,2t+1,2t+8,2t+9} <-> physical 4t..4t+3,
    // shared by A and B fragments so the dot product is order-invariant)
    const float* xp = x + (size_t)(tok0 + wid * 32 + gid) * DK + tig * 4;
    // B fragment-major pointer: per group stride = 8 ntiles * 32 lanes
    const uint4* bfp = g_Bfrag + lane;

    float acc[2][8][4];
#pragma unroll
    for (int mt = 0; mt < 2; mt++)
#pragma unroll
        for (int nt = 0; nt < 8; nt++)
#pragma unroll
            for (int q = 0; q < 4; q++) acc[mt][nt][q] = 0.0f;

    // double buffers
    float4 abuf[2][2][2];     // [buf][m-tile][row-half]
    uint4  bbuf[2][8];        // [buf][ntile]

    // prologue: group 0 -> buffer 0
#pragma unroll
    for (int mt = 0; mt < 2; mt++) {
        abuf[0][mt][0] = *reinterpret_cast<const float4*>(xp + (mt * 16 + 0) * DK);
        abuf[0][mt][1] = *reinterpret_cast<const float4*>(xp + (mt * 16 + 8) * DK);
    }
#pragma unroll
    for (int nt = 0; nt < 8; nt++)
        bbuf[0][nt] = bfp[nt * 32];

#pragma unroll 2
    for (int g = 0; g < NGROUPS; ++g) {
        const int cur = g & 1;
        const int nxt = cur ^ 1;

        // ---- prefetch group g+1 into the other buffer ----
        if (g + 1 < NGROUPS) {
            const int kt = (g + 1) * 16;
#pragma unroll
            for (int mt = 0; mt < 2; mt++) {
                abuf[nxt][mt][0] = *reinterpret_cast<const float4*>(xp + (mt * 16 + 0) * DK + kt);
                abuf[nxt][mt][1] = *reinterpret_cast<const float4*>(xp + (mt * 16 + 8) * DK + kt);
            }
            const uint4* bg = bfp + (size_t)(g + 1) * 256;
#pragma unroll
            for (int nt = 0; nt < 8; nt++)
                bbuf[nxt][nt] = bg[nt * 32];
        }

        // ---- split A into fp16 hi/lo fragments ----
        uint32_t ah[2][4], al[2][4];
#pragma unroll
        for (int mt = 0; mt < 2; mt++) {
            split2(make_float2(abuf[cur][mt][0].x, abuf[cur][mt][0].y), ah[mt][0], al[mt][0]);
            split2(make_float2(abuf[cur][mt][1].x, abuf[cur][mt][1].y), ah[mt][1], al[mt][1]);
            split2(make_float2(abuf[cur][mt][0].z, abuf[cur][mt][0].w), ah[mt][2], al[mt][2]);
            split2(make_float2(abuf[cur][mt][1].z, abuf[cur][mt][1].w), ah[mt][3], al[mt][3]);
        }

        // ---- 3 products per tile: hi*hi + hi*lo + lo*hi ----
#pragma unroll
        for (int nt = 0; nt < 8; nt++) {
            const uint4 b = bbuf[cur][nt];
#pragma unroll
            for (int mt = 0; mt < 2; mt++) {
                mma16(acc[mt][nt], ah[mt], b.x, b.y);   // hi*hi
                mma16(acc[mt][nt], ah[mt], b.z, b.w);   // hi*lo
                mma16(acc[mt][nt], al[mt], b.x, b.y);   // lo*hi
            }
        }
    }

    // ---- epilogue: accumulators -> smem logits ----
#pragma unroll
    for (int mt = 0; mt < 2; mt++)
#pragma unroll
        for (int nt = 0; nt < 8; nt++) {
            const int r = wid * 32 + mt * 16 + gid;
            const int e = nt * 8 + 2 * tig;
            lg[r][e]         = acc[mt][nt][0];
            lg[r][e + 1]     = acc[mt][nt][1];
            lg[r + 8][e]     = acc[mt][nt][2];
            lg[r + 8][e + 1] = acc[mt][nt][3];
        }
    __syncthreads();

    float* out_gates = out;
    float* out_idx   = out + 2 * NTOK;
    float* out_load  = out + 4 * NTOK;
    float* out_tlog  = out + 4 * NTOK + NE;

    {
        const float* row = lg[tid];
        // jax.lax.top_k tie-break: lowest index wins -> strict '>' ascending scan
        float m1 = -1e30f, m2 = -1e30f;
        int   i1 = 0,      i2 = 0;
#pragma unroll 8
        for (int e = 0; e < NE; e++) {
            float v = row[e];
            if (v > m1)      { m2 = m1; i2 = i1; m1 = v; i1 = e; }
            else if (v > m2) { m2 = v;  i2 = e; }
        }
        float ex  = expf(m2 - m1);      // stable: m1 >= m2
        float inv = 1.0f / (1.0f + ex);
        float g1  = inv;
        float g2  = ex * inv;

        const int t = tok0 + tid;
        reinterpret_cast<float2*>(out_gates)[t] = make_float2(g1, g2);
        reinterpret_cast<float2*>(out_idx)[t]   = make_float2((float)i1, (float)i2);
        reinterpret_cast<float2*>(out_tlog)[t]  = make_float2(m1, m2);

        sg[2 * tid] = g1;  sg[2 * tid + 1] = g2;
        si[2 * tid] = i1;  si[2 * tid + 1] = i2;
    }
    __syncthreads();

    // per-CTA deterministic expert-load partial, one atomic per expert per CTA
    if (tid < NE) {
        float ssum = 0.0f;
#pragma unroll 8
        for (int n = 0; n < 2 * BM; n++)
            ssum += (si[n] == tid) ? sg[n] : 0.0f;
        atomicAdd(out_load + tid, ssum);
    }
}

// ---------------------------------------------------------------------------
extern "C" void kernel_launch(void* const* d_in, const int* in_sizes, int n_in,
                              void* d_out, int out_size) {
    const float* x = (const float*)d_in[0];   // [32768, 2048]
    const float* w = (const float*)d_in[1];   // [64, 2048]
    float* out = (float*)d_out;

    prep_kernel<<<128, 256>>>(w, out + 4 * NTOK);      // frag-major B limbs + zero load
    router_kernel<<<NTOK / BM, NTHREADS>>>(x, out);
}

// round 8
// speedup vs baseline: 1.0631x; 1.0631x over previous
#include <cuda_runtime.h>
#include <cuda_fp16.h>
#include <cstdint>

// ---------------------------------------------------------------------------
// ModalityRouter via mma.sync m16n8k16.f16 with 2-limb fp32 split (3 products)
// R6 shape (8 warps, M32xN32/warp, frag-major B) + product-major MMA ordering
// to break accumulator RAW chains.
//   logits = x @ gate_w^T ; top-2 ; softmax ; expert load
//   x: [32768, 2048] fp32   gate_w: [64, 2048] fp32
// Output fp32: gates[65536] | idx[65536] | load[64] | top_logits[65536]
// ---------------------------------------------------------------------------

#define DK        2048
#define NE        64
#define NTOK      32768
#define BM        128
#define NTHREADS  256
#define NGROUPS   (DK / 16)      // 128 groups of 16 k-columns

// fragment-major fp16 limb split of gate_w:
//   g_Bfrag[((es*NGROUPS + g)*4 + nt)*32 + lane] = {hi.x, hi.y, lo.x, lo.y}
//   lane=(gid*4+tig) holds halves k = g*16 + perm(tig*4..+3) of expert
//   e = es*32 + nt*8 + gid   (same k-permutation as the A fragments)
__device__ uint4 g_Bfrag[2 * NGROUPS * 4 * 32];     // 512 KB

__device__ __forceinline__ uint32_t pack_h2(float a, float b) {
    __half2 h = __halves2half2(__float2half_rn(a), __float2half_rn(b));
    return *reinterpret_cast<uint32_t*>(&h);
}

__global__ void prep_kernel(const float* __restrict__ w, float* __restrict__ out_load) {
    const int t = blockIdx.x * 256 + threadIdx.x;    // 32768 threads total
    if (blockIdx.x == 0 && threadIdx.x < NE) out_load[threadIdx.x] = 0.0f;

    const int lane = t & 31;
    const int nt   = (t >> 5) & 3;
    const int g    = (t >> 7) & (NGROUPS - 1);
    const int es   = t >> 14;
    const int gid  = lane >> 2;
    const int tig  = lane & 3;
    const int e    = es * 32 + nt * 8 + gid;
    const int kb   = g * 16 + tig * 4;

    float4 v = *reinterpret_cast<const float4*>(w + (size_t)e * DK + kb);
    float hx = __half2float(__float2half_rn(v.x));
    float hy = __half2float(__float2half_rn(v.y));
    float hz = __half2float(__float2half_rn(v.z));
    float hw = __half2float(__float2half_rn(v.w));

    uint4 frag;
    frag.x = pack_h2(v.x, v.y);                 // hi limb, k {4t, 4t+1}
    frag.y = pack_h2(v.z, v.w);                 // hi limb, k {4t+2, 4t+3}
    frag.z = pack_h2(v.x - hx, v.y - hy);       // lo limb
    frag.w = pack_h2(v.z - hz, v.w - hw);
    g_Bfrag[t] = frag;
}

// warp-level tensor op: D += A(f16) * B(f16), f32 accumulate
__device__ __forceinline__ void mma16(float* d, const uint32_t* a,
                                      uint32_t b0, uint32_t b1) {
    asm volatile(
        "mma.sync.aligned.m16n8k16.row.col.f32.f16.f16.f32 "
        "{%0,%1,%2,%3}, {%4,%5,%6,%7}, {%8,%9}, {%0,%1,%2,%3};"
        : "+f"(d[0]), "+f"(d[1]), "+f"(d[2]), "+f"(d[3])
        : "r"(a[0]), "r"(a[1]), "r"(a[2]), "r"(a[3]), "r"(b0), "r"(b1));
}

// split a float2 into (hi half2, lo half2)
__device__ __forceinline__ void split2(float2 f, uint32_t& hi, uint32_t& lo) {
    __half2 h = __float22half2_rn(f);
    float2 hf = __half22float2(h);
    __half2 l = __float22half2_rn(make_float2(f.x - hf.x, f.y - hf.y));
    hi = *reinterpret_cast<uint32_t*>(&h);
    lo = *reinterpret_cast<uint32_t*>(&l);
}

// ---------------------------------------------------------------------------
__global__ void __launch_bounds__(NTHREADS, 2)
router_kernel(const float* __restrict__ x, float* __restrict__ out)
{
    __shared__ float lg[BM][NE + 1];
    __shared__ float sg[2 * BM];
    __shared__ int   si[2 * BM];

    const int tid    = threadIdx.x;
    const int wid    = tid >> 5;
    const int lane   = tid & 31;
    const int gid    = lane >> 2;       // fragment row/col group (0..7)
    const int tig    = lane & 3;        // thread-in-group (0..3)
    const int tslice = wid >> 1;        // token slice (0..3): 32 tokens each
    const int eslice = wid & 1;         // expert slice (0..1): 32 experts each
    const int tok0   = blockIdx.x * BM;

    // A pointer (k-permutation {2t,2t+1,2t+8,2t+9} <-> physical 4t..4t+3,
    // shared by A and B fragments so the dot product is order-invariant)
    const float* xp = x + (size_t)(tok0 + tslice * 32 + gid) * DK + tig * 4;
    // B fragment-major pointer: per group stride = 4 ntiles * 32 lanes
    const uint4* bfp = g_Bfrag + (size_t)eslice * NGROUPS * 4 * 32 + lane;

    float acc[2][4][4];
#pragma unroll
    for (int mt = 0; mt < 2; mt++)
#pragma unroll
        for (int nt = 0; nt < 4; nt++)
#pragma unroll
            for (int q = 0; q < 4; q++) acc[mt][nt][q] = 0.0f;

    // double buffers
    float4 abuf[2][2][2];     // [buf][m-tile][row-half]
    uint4  bbuf[2][4];        // [buf][ntile]

    // prologue: group 0 -> buffer 0
#pragma unroll
    for (int mt = 0; mt < 2; mt++) {
        abuf[0][mt][0] = *reinterpret_cast<const float4*>(xp + (mt * 16 + 0) * DK);
        abuf[0][mt][1] = *reinterpret_cast<const float4*>(xp + (mt * 16 + 8) * DK);
    }
#pragma unroll
    for (int nt = 0; nt < 4; nt++)
        bbuf[0][nt] = bfp[nt * 32];

#pragma unroll 2
    for (int g = 0; g < NGROUPS; ++g) {
        const int cur = g & 1;
        const int nxt = cur ^ 1;

        // ---- prefetch group g+1 into the other buffer ----
        if (g + 1 < NGROUPS) {
            const int kt = (g + 1) * 16;
#pragma unroll
            for (int mt = 0; mt < 2; mt++) {
                abuf[nxt][mt][0] = *reinterpret_cast<const float4*>(xp + (mt * 16 + 0) * DK + kt);
                abuf[nxt][mt][1] = *reinterpret_cast<const float4*>(xp + (mt * 16 + 8) * DK + kt);
            }
            const uint4* bg = bfp + (size_t)(g + 1) * 128;
#pragma unroll
            for (int nt = 0; nt < 4; nt++)
                bbuf[nxt][nt] = bg[nt * 32];
        }

        // ---- split A into fp16 hi/lo fragments ----
        uint32_t ah[2][4], al[2][4];
#pragma unroll
        for (int mt = 0; mt < 2; mt++) {
            split2(make_float2(abuf[cur][mt][0].x, abuf[cur][mt][0].y), ah[mt][0], al[mt][0]);
            split2(make_float2(abuf[cur][mt][1].x, abuf[cur][mt][1].y), ah[mt][1], al[mt][1]);
            split2(make_float2(abuf[cur][mt][0].z, abuf[cur][mt][0].w), ah[mt][2], al[mt][2]);
            split2(make_float2(abuf[cur][mt][1].z, abuf[cur][mt][1].w), ah[mt][3], al[mt][3]);
        }

        // ---- product-major MMA ordering: same-acc MMAs are 8 apart (no RAW stall)
#pragma unroll
        for (int nt = 0; nt < 4; nt++)           // pass 1: hi*hi
#pragma unroll
            for (int mt = 0; mt < 2; mt++)
                mma16(acc[mt][nt], ah[mt], bbuf[cur][nt].x, bbuf[cur][nt].y);
#pragma unroll
        for (int nt = 0; nt < 4; nt++)           // pass 2: hi*lo
#pragma unroll
            for (int mt = 0; mt < 2; mt++)
                mma16(acc[mt][nt], ah[mt], bbuf[cur][nt].z, bbuf[cur][nt].w);
#pragma unroll
        for (int nt = 0; nt < 4; nt++)           // pass 3: lo*hi
#pragma unroll
            for (int mt = 0; mt < 2; mt++)
                mma16(acc[mt][nt], al[mt], bbuf[cur][nt].x, bbuf[cur][nt].y);
    }

    // ---- epilogue: accumulators -> smem logits ----
#pragma unroll
    for (int mt = 0; mt < 2; mt++)
#pragma unroll
        for (int nt = 0; nt < 4; nt++) {
            const int r = tslice * 32 + mt * 16 + gid;
            const int e = eslice * 32 + nt * 8 + 2 * tig;
            lg[r][e]         = acc[mt][nt][0];
            lg[r][e + 1]     = acc[mt][nt][1];
            lg[r + 8][e]     = acc[mt][nt][2];
            lg[r + 8][e + 1] = acc[mt][nt][3];
        }
    __syncthreads();

    float* out_gates = out;
    float* out_idx   = out + 2 * NTOK;
    float* out_load  = out + 4 * NTOK;
    float* out_tlog  = out + 4 * NTOK + NE;

    if (tid < BM) {
        const float* row = lg[tid];
        // jax.lax.top_k tie-break: lowest index wins -> strict '>' ascending scan
        float m1 = -1e30f, m2 = -1e30f;
        int   i1 = 0,      i2 = 0;
#pragma unroll 8
        for (int e = 0; e < NE; e++) {
            float v = row[e];
            if (v > m1)      { m2 = m1; i2 = i1; m1 = v; i1 = e; }
            else if (v > m2) { m2 = v;  i2 = e; }
        }
        float ex  = expf(m2 - m1);      // stable: m1 >= m2
        float inv = 1.0f / (1.0f + ex);
        float g1  = inv;
        float g2  = ex * inv;

        const int t = tok0 + tid;
        reinterpret_cast<float2*>(out_gates)[t] = make_float2(g1, g2);
        reinterpret_cast<float2*>(out_idx)[t]   = make_float2((float)i1, (float)i2);
        reinterpret_cast<float2*>(out_tlog)[t]  = make_float2(m1, m2);

        sg[2 * tid] = g1;  sg[2 * tid + 1] = g2;
        si[2 * tid] = i1;  si[2 * tid + 1] = i2;
    }
    __syncthreads();

    // per-CTA deterministic expert-load partial, one atomic per expert per CTA
    if (tid < NE) {
        float ssum = 0.0f;
#pragma unroll 8
        for (int n = 0; n < 2 * BM; n++)
            ssum += (si[n] == tid) ? sg[n] : 0.0f;
        atomicAdd(out_load + tid, ssum);
    }
}

// ---------------------------------------------------------------------------
extern "C" void kernel_launch(void* const* d_in, const int* in_sizes, int n_in,
                              void* d_out, int out_size) {
    const float* x = (const float*)d_in[0];   // [32768, 2048]
    const float* w = (const float*)d_in[1];   // [64, 2048]
    float* out = (float*)d_out;

    prep_kernel<<<128, 256>>>(w, out + 4 * NTOK);      // frag-major B limbs + zero load
    router_kernel<<<NTOK / BM, NTHREADS>>>(x, out);
}